// round 1
// baseline (speedup 1.0000x reference)
#include <cuda_runtime.h>
#include <math.h>

// Problem constants
#define DIMC   2048
#define NH     16
#define NKV    4
#define HD     128
#define BATCH  2
#define SEQ    2048
#define MROWS  (BATCH*SEQ)     // 4096
#define KVDIM  (NKV*HD)        // 512

// Scratch (no cudaMalloc allowed)
__device__ float g_q[MROWS * DIMC];    // 32 MB
__device__ float g_k[MROWS * KVDIM];   //  8 MB
__device__ float g_v[MROWS * KVDIM];   //  8 MB
__device__ float g_att[MROWS * DIMC];  // 32 MB

// ---------------------------------------------------------------------------
// Classic 128x128x8 register-tiled SGEMM. C = A(MxK) @ B(KxN), all row-major.
// Requires M%128==0, N%128==0, K%8==0 (true for all our shapes).
// 256 threads, each computes an 8x8 micro-tile.
// ---------------------------------------------------------------------------
__global__ __launch_bounds__(256) void sgemm128(
    const float* __restrict__ A, const float* __restrict__ Bm,
    float* __restrict__ C, int M, int N, int K)
{
    __shared__ float As[8][128];   // transposed A tile: As[k][m]
    __shared__ float Bs[8][128];   // Bs[k][n]

    const int tid = threadIdx.x;
    const int bm = blockIdx.y * 128;
    const int bn = blockIdx.x * 128;
    const int tx = tid & 15;       // 0..15  -> n micro
    const int ty = tid >> 4;       // 0..15  -> m micro

    // load mapping
    const int ar = tid >> 1;             // 0..127 (A tile row)
    const int ac = (tid & 1) * 4;        // 0 or 4 (A tile col base)
    const int br = tid >> 5;             // 0..7   (B tile row)
    const int bc = (tid & 31) * 4;       // B tile col base

    float acc[8][8];
    #pragma unroll
    for (int i = 0; i < 8; i++)
        #pragma unroll
        for (int j = 0; j < 8; j++) acc[i][j] = 0.f;

    for (int k0 = 0; k0 < K; k0 += 8) {
        float4 a4 = *reinterpret_cast<const float4*>(&A[(size_t)(bm + ar) * K + k0 + ac]);
        float4 b4 = *reinterpret_cast<const float4*>(&Bm[(size_t)(k0 + br) * N + bn + bc]);
        As[ac + 0][ar] = a4.x;
        As[ac + 1][ar] = a4.y;
        As[ac + 2][ar] = a4.z;
        As[ac + 3][ar] = a4.w;
        *reinterpret_cast<float4*>(&Bs[br][bc]) = b4;
        __syncthreads();

        #pragma unroll
        for (int kk = 0; kk < 8; kk++) {
            float a[8], b[8];
            #pragma unroll
            for (int i = 0; i < 8; i++) a[i] = As[kk][ty * 8 + i];
            #pragma unroll
            for (int j = 0; j < 8; j++) b[j] = Bs[kk][tx * 8 + j];
            #pragma unroll
            for (int i = 0; i < 8; i++)
                #pragma unroll
                for (int j = 0; j < 8; j++)
                    acc[i][j] = fmaf(a[i], b[j], acc[i][j]);
        }
        __syncthreads();
    }

    #pragma unroll
    for (int i = 0; i < 8; i++) {
        float4* dst = reinterpret_cast<float4*>(&C[(size_t)(bm + ty * 8 + i) * N + bn + tx * 8]);
        dst[0] = make_float4(acc[i][0], acc[i][1], acc[i][2], acc[i][3]);
        dst[1] = make_float4(acc[i][4], acc[i][5], acc[i][6], acc[i][7]);
    }
}

// ---------------------------------------------------------------------------
// Flash attention, fp32, online softmax. One block = (batch b, head h, 64 q rows).
// Br = Bc = 64, d = 128. 256 threads.
// S phase: thread (ty,tx) computes S[ty*4..+3][tx*4..+3].
// O phase: thread (ty,tx) accumulates O[ty*4..+3][tx*8..+7].
// Row stats reduced across the 16 threads sharing a ty (half-warp shuffles).
// ---------------------------------------------------------------------------
#define BR 64
#define BC 64
#define QK_PAD 129                      // 64x129 padded rows (bank-conflict free)
#define FLASH_SMEM_FLOATS (2*64*QK_PAD + 64*128 + 64*65)

__global__ __launch_bounds__(256) void flash_fp32(
    const float* __restrict__ Q,   // [MROWS][DIMC]
    const float* __restrict__ Kg,  // [MROWS][KVDIM]
    const float* __restrict__ Vg,  // [MROWS][KVDIM]
    float* __restrict__ Og)        // [MROWS][DIMC]
{
    extern __shared__ float sm[];
    float (*Qs)[QK_PAD] = (float(*)[QK_PAD])sm;
    float (*Ks)[QK_PAD] = (float(*)[QK_PAD])(sm + 64 * QK_PAD);
    float (*Vs)[128]    = (float(*)[128])(sm + 2 * 64 * QK_PAD);
    float (*Ss)[65]     = (float(*)[65])(sm + 2 * 64 * QK_PAD + 64 * 128);

    const int tid = threadIdx.x;
    const int qb  = blockIdx.x;           // query tile 0..31
    const int h   = blockIdx.y;           // head 0..15
    const int b   = blockIdx.z;           // batch
    const int kh  = h >> 2;               // kv head (G = 4)
    const int q_row0 = b * SEQ + qb * BR;
    const int k_row0 = b * SEQ;
    const float scale = 0.08838834764831845f;   // 1/sqrt(128)

    // Load Q tile (pre-scaled)
    for (int idx = tid; idx < BR * HD; idx += 256) {
        int r = idx >> 7, c = idx & 127;
        Qs[r][c] = Q[(size_t)(q_row0 + r) * DIMC + h * HD + c] * scale;
    }

    const int tx = tid & 15;
    const int ty = tid >> 4;

    float m_r[4], l_r[4], oacc[4][8];
    #pragma unroll
    for (int i = 0; i < 4; i++) {
        m_r[i] = -INFINITY; l_r[i] = 0.f;
        #pragma unroll
        for (int j = 0; j < 8; j++) oacc[i][j] = 0.f;
    }

    for (int s0 = 0; s0 < SEQ; s0 += BC) {
        __syncthreads();   // previous tile's Vs/Ss reads done
        // Load K, V tiles
        for (int idx = tid; idx < BC * HD; idx += 256) {
            int r = idx >> 7, c = idx & 127;
            Ks[r][c] = Kg[(size_t)(k_row0 + s0 + r) * KVDIM + kh * HD + c];
        }
        for (int idx = tid * 4; idx < BC * HD; idx += 1024) {
            int r = idx >> 7, c = idx & 127;
            *reinterpret_cast<float4*>(&Vs[r][c]) =
                *reinterpret_cast<const float4*>(&Vg[(size_t)(k_row0 + s0 + r) * KVDIM + kh * HD + c]);
        }
        __syncthreads();

        // S = (Q*scale) @ K^T : 4x4 micro-tile per thread
        float s[4][4];
        #pragma unroll
        for (int i = 0; i < 4; i++)
            #pragma unroll
            for (int j = 0; j < 4; j++) s[i][j] = 0.f;

        #pragma unroll 4
        for (int dd = 0; dd < HD; dd++) {
            float qv[4], kv[4];
            #pragma unroll
            for (int i = 0; i < 4; i++) qv[i] = Qs[ty * 4 + i][dd];
            #pragma unroll
            for (int j = 0; j < 4; j++) kv[j] = Ks[tx * 4 + j][dd];
            #pragma unroll
            for (int i = 0; i < 4; i++)
                #pragma unroll
                for (int j = 0; j < 4; j++)
                    s[i][j] = fmaf(qv[i], kv[j], s[i][j]);
        }

        // Online softmax update (per row; 16 threads share a row via half-warp shuffle)
        #pragma unroll
        for (int i = 0; i < 4; i++) {
            float rmax = fmaxf(fmaxf(s[i][0], s[i][1]), fmaxf(s[i][2], s[i][3]));
            #pragma unroll
            for (int o = 8; o > 0; o >>= 1)
                rmax = fmaxf(rmax, __shfl_xor_sync(0xffffffffu, rmax, o));
            float m_new = fmaxf(m_r[i], rmax);
            float rsum = 0.f;
            #pragma unroll
            for (int j = 0; j < 4; j++) {
                float p = __expf(s[i][j] - m_new);
                Ss[ty * 4 + i][tx * 4 + j] = p;
                rsum += p;
            }
            #pragma unroll
            for (int o = 8; o > 0; o >>= 1)
                rsum += __shfl_xor_sync(0xffffffffu, rsum, o);
            float alpha = __expf(m_r[i] - m_new);
            l_r[i] = l_r[i] * alpha + rsum;
            m_r[i] = m_new;
            #pragma unroll
            for (int j = 0; j < 8; j++) oacc[i][j] *= alpha;
        }
        __syncthreads();

        // O += P @ V
        #pragma unroll 2
        for (int jj = 0; jj < BC; jj++) {
            float p[4];
            #pragma unroll
            for (int i = 0; i < 4; i++) p[i] = Ss[ty * 4 + i][jj];
            float4 v0 = *reinterpret_cast<const float4*>(&Vs[jj][tx * 8]);
            float4 v1 = *reinterpret_cast<const float4*>(&Vs[jj][tx * 8 + 4]);
            float vv[8] = {v0.x, v0.y, v0.z, v0.w, v1.x, v1.y, v1.z, v1.w};
            #pragma unroll
            for (int i = 0; i < 4; i++)
                #pragma unroll
                for (int c = 0; c < 8; c++)
                    oacc[i][c] = fmaf(p[i], vv[c], oacc[i][c]);
        }
    }

    // Epilogue: normalize and store
    #pragma unroll
    for (int i = 0; i < 4; i++) {
        float inv = 1.f / l_r[i];
        float* dst = &Og[(size_t)(q_row0 + ty * 4 + i) * DIMC + h * HD + tx * 8];
        float4 o0 = make_float4(oacc[i][0] * inv, oacc[i][1] * inv, oacc[i][2] * inv, oacc[i][3] * inv);
        float4 o1 = make_float4(oacc[i][4] * inv, oacc[i][5] * inv, oacc[i][6] * inv, oacc[i][7] * inv);
        reinterpret_cast<float4*>(dst)[0] = o0;
        reinterpret_cast<float4*>(dst)[1] = o1;
    }
}

// ---------------------------------------------------------------------------
extern "C" void kernel_launch(void* const* d_in, const int* in_sizes, int n_in,
                              void* d_out, int out_size)
{
    const float* x  = (const float*)d_in[0];
    const float* Wq = (const float*)d_in[1];
    const float* Wk = (const float*)d_in[2];
    const float* Wv = (const float*)d_in[3];
    const float* Wo = (const float*)d_in[4];
    float* out = (float*)d_out;

    float *q, *k, *v, *att;
    cudaGetSymbolAddress((void**)&q,   g_q);
    cudaGetSymbolAddress((void**)&k,   g_k);
    cudaGetSymbolAddress((void**)&v,   g_v);
    cudaGetSymbolAddress((void**)&att, g_att);

    const size_t flash_smem = FLASH_SMEM_FLOATS * sizeof(float);  // ~115.5 KB
    cudaFuncSetAttribute(flash_fp32, cudaFuncAttributeMaxDynamicSharedMemorySize,
                         (int)flash_smem);

    dim3 blk(256);
    dim3 gq(DIMC / 128, MROWS / 128);   // (16, 32)
    dim3 gkv(KVDIM / 128, MROWS / 128); // (4, 32)

    sgemm128<<<gq,  blk>>>(x, Wq, q, MROWS, DIMC,  DIMC);
    sgemm128<<<gkv, blk>>>(x, Wk, k, MROWS, KVDIM, DIMC);
    sgemm128<<<gkv, blk>>>(x, Wv, v, MROWS, KVDIM, DIMC);

    flash_fp32<<<dim3(SEQ / BR, NH, BATCH), blk, flash_smem>>>(q, k, v, att);

    sgemm128<<<gq, blk>>>(att, Wo, out, MROWS, DIMC, DIMC);
}

// round 2
// speedup vs baseline: 3.1856x; 3.1856x over previous
#include <cuda_runtime.h>
#include <math.h>
#include <stdint.h>

#define DIMC   2048
#define NH     16
#define NKV    4
#define HD     128
#define BATCH  2
#define SEQ    2048
#define MROWS  (BATCH*SEQ)     // 4096
#define KVDIM  (NKV*HD)        // 512

// Scratch (no cudaMalloc allowed)
__device__ float g_q[MROWS * DIMC];
__device__ float g_k[MROWS * KVDIM];
__device__ float g_v[MROWS * KVDIM];
__device__ float g_att[MROWS * DIMC];

// ---------------------------------------------------------------------------
// tf32 helpers
// ---------------------------------------------------------------------------
__device__ __forceinline__ uint32_t f2tf32(float x) {
    uint32_t u;
    asm("cvt.rna.tf32.f32 %0, %1;" : "=r"(u) : "f"(x));
    return u;
}
__device__ __forceinline__ float f2tf32f(float x) {
    return __uint_as_float(f2tf32(x));
}

__device__ __forceinline__ void mma_tf32(float* c,
    uint32_t a0, uint32_t a1, uint32_t a2, uint32_t a3,
    uint32_t b0, uint32_t b1)
{
    asm volatile(
        "mma.sync.aligned.m16n8k8.row.col.f32.tf32.tf32.f32 "
        "{%0,%1,%2,%3}, {%4,%5,%6,%7}, {%8,%9}, {%0,%1,%2,%3};"
        : "+f"(c[0]), "+f"(c[1]), "+f"(c[2]), "+f"(c[3])
        : "r"(a0), "r"(a1), "r"(a2), "r"(a3), "r"(b0), "r"(b1));
}

// ---------------------------------------------------------------------------
// tf32 tensor-core GEMM: C = A(MxK) @ B(KxN), row-major, fp32 in/out.
// Block tile 128x128, BK=32, 256 threads (8 warps, 2(m) x 4(n)).
// Warp tile 64x32 -> 4 m-tiles(16) x 4 n-tiles(8). Single smem buffer with
// register prefetch double buffering.
// Requires M%128==0, N%128==0, K%32==0.
// ---------------------------------------------------------------------------
#define GBK 32
#define AS_ST 36     // 32 + 4 pad
#define BS_ST 132    // 128 + 4 pad

__global__ __launch_bounds__(256) void gemm_tf32(
    const float* __restrict__ A, const float* __restrict__ B,
    float* __restrict__ C, int M, int N, int K)
{
    __shared__ float As[128][AS_ST];   // [m][k]
    __shared__ float Bs[GBK][BS_ST];   // [k][n]

    const int tid  = threadIdx.x;
    const int warp = tid >> 5;
    const int lane = tid & 31;
    const int g = lane >> 2;           // 0..7
    const int t = lane & 3;            // 0..3
    const int wm = warp & 1;           // 0..1
    const int wn = warp >> 1;          // 0..3
    const int bm = blockIdx.y * 128;
    const int bn = blockIdx.x * 128;

    float acc[4][4][4];
    #pragma unroll
    for (int i = 0; i < 4; i++)
        #pragma unroll
        for (int j = 0; j < 4; j++)
            #pragma unroll
            for (int r = 0; r < 4; r++) acc[i][j][r] = 0.f;

    // global load mapping (per tile): 4 float4 each for A and B
    // A: f = tid + i*256 : row = f>>3, kcol = (f&7)*4
    // B: f = tid + i*256 : krow = f>>5, col = (f&31)*4
    float4 pa[4], pb[4];

    #pragma unroll
    for (int i = 0; i < 4; i++) {
        int f = tid + i * 256;
        pa[i] = *reinterpret_cast<const float4*>(&A[(size_t)(bm + (f >> 3)) * K + ((f & 7) * 4)]);
        pb[i] = *reinterpret_cast<const float4*>(&B[(size_t)(f >> 5) * N + bn + (f & 31) * 4]);
    }
    // store tile 0 (with tf32 rounding)
    #pragma unroll
    for (int i = 0; i < 4; i++) {
        int f = tid + i * 256;
        float4 va = make_float4(f2tf32f(pa[i].x), f2tf32f(pa[i].y), f2tf32f(pa[i].z), f2tf32f(pa[i].w));
        *reinterpret_cast<float4*>(&As[f >> 3][(f & 7) * 4]) = va;
        float4 vb = make_float4(f2tf32f(pb[i].x), f2tf32f(pb[i].y), f2tf32f(pb[i].z), f2tf32f(pb[i].w));
        *reinterpret_cast<float4*>(&Bs[f >> 5][(f & 31) * 4]) = vb;
    }
    __syncthreads();

    for (int k0 = 0; k0 < K; k0 += GBK) {
        const bool has_next = (k0 + GBK < K);
        if (has_next) {
            #pragma unroll
            for (int i = 0; i < 4; i++) {
                int f = tid + i * 256;
                pa[i] = *reinterpret_cast<const float4*>(&A[(size_t)(bm + (f >> 3)) * K + k0 + GBK + ((f & 7) * 4)]);
                pb[i] = *reinterpret_cast<const float4*>(&B[(size_t)(k0 + GBK + (f >> 5)) * N + bn + (f & 31) * 4]);
            }
        }

        #pragma unroll
        for (int ks = 0; ks < 4; ks++) {
            const int kk = ks * 8;
            uint32_t af[4][4], bf[4][2];
            #pragma unroll
            for (int mt = 0; mt < 4; mt++) {
                int r = wm * 64 + mt * 16;
                af[mt][0] = __float_as_uint(As[r + g][kk + t]);
                af[mt][1] = __float_as_uint(As[r + g + 8][kk + t]);
                af[mt][2] = __float_as_uint(As[r + g][kk + t + 4]);
                af[mt][3] = __float_as_uint(As[r + g + 8][kk + t + 4]);
            }
            #pragma unroll
            for (int nt = 0; nt < 4; nt++) {
                int c = wn * 32 + nt * 8 + g;
                bf[nt][0] = __float_as_uint(Bs[kk + t][c]);
                bf[nt][1] = __float_as_uint(Bs[kk + t + 4][c]);
            }
            #pragma unroll
            for (int mt = 0; mt < 4; mt++)
                #pragma unroll
                for (int nt = 0; nt < 4; nt++)
                    mma_tf32(acc[mt][nt], af[mt][0], af[mt][1], af[mt][2], af[mt][3],
                             bf[nt][0], bf[nt][1]);
        }

        if (has_next) {
            __syncthreads();   // everyone done reading current tile
            #pragma unroll
            for (int i = 0; i < 4; i++) {
                int f = tid + i * 256;
                float4 va = make_float4(f2tf32f(pa[i].x), f2tf32f(pa[i].y), f2tf32f(pa[i].z), f2tf32f(pa[i].w));
                *reinterpret_cast<float4*>(&As[f >> 3][(f & 7) * 4]) = va;
                float4 vb = make_float4(f2tf32f(pb[i].x), f2tf32f(pb[i].y), f2tf32f(pb[i].z), f2tf32f(pb[i].w));
                *reinterpret_cast<float4*>(&Bs[f >> 5][(f & 31) * 4]) = vb;
            }
            __syncthreads();
        }
    }

    // epilogue
    #pragma unroll
    for (int mt = 0; mt < 4; mt++) {
        #pragma unroll
        for (int nt = 0; nt < 4; nt++) {
            int r0 = bm + wm * 64 + mt * 16 + g;
            int c0 = bn + wn * 32 + nt * 8 + 2 * t;
            *reinterpret_cast<float2*>(&C[(size_t)r0 * N + c0]) =
                make_float2(acc[mt][nt][0], acc[mt][nt][1]);
            *reinterpret_cast<float2*>(&C[(size_t)(r0 + 8) * N + c0]) =
                make_float2(acc[mt][nt][2], acc[mt][nt][3]);
        }
    }
}

// ---------------------------------------------------------------------------
// Flash attention with tf32 tensor cores. Br=128, Bc=64, d=128.
// 256 threads = 8 warps; warp w owns query rows [16w, 16w+16) -> softmax is
// warp-private (no cross-warp reductions). Q fragments live in registers for
// the whole kernel. S accumulated in regs, P round-trips through smem (tf32-
// rounded so PV matches the l normalizer exactly).
// ---------------------------------------------------------------------------
#define FBR 128
#define FBC 64
#define KV_ST 132   // 128 + 4
#define PS_ST 68    // 64 + 4
#define FLASH_SMEM_BYTES ((2*FBC*KV_ST + FBR*PS_ST) * 4)   // 102400 B

__global__ __launch_bounds__(256) void flash_tf32(
    const float* __restrict__ Q,   // [MROWS][DIMC]
    const float* __restrict__ Kg,  // [MROWS][KVDIM]
    const float* __restrict__ Vg,  // [MROWS][KVDIM]
    float* __restrict__ Og)        // [MROWS][DIMC]
{
    extern __shared__ float sm[];
    float (*Ks)[KV_ST] = (float(*)[KV_ST])sm;
    float (*Vs)[KV_ST] = (float(*)[KV_ST])(sm + FBC * KV_ST);
    float (*Ps)[PS_ST] = (float(*)[PS_ST])(sm + 2 * FBC * KV_ST);

    const int tid  = threadIdx.x;
    const int warp = tid >> 5;
    const int lane = tid & 31;
    const int g = lane >> 2;
    const int t = lane & 3;

    const int qb = blockIdx.x;         // 0..15
    const int h  = blockIdx.y;         // 0..15
    const int b  = blockIdx.z;
    const int kh = h >> 2;
    const int q0 = b * SEQ + qb * FBR;
    const int kbase = b * SEQ;
    const float scale = 0.08838834764831845f;  // 1/sqrt(128)

    // Q fragments: 16 k-steps x 4 regs, pre-scaled + tf32 rounded
    uint32_t qf[16][4];
    {
        const float* Qb = Q + (size_t)(q0 + warp * 16) * DIMC + h * HD;
        #pragma unroll
        for (int ks = 0; ks < 16; ks++) {
            int kk = ks * 8;
            qf[ks][0] = f2tf32(scale * Qb[(size_t)g * DIMC + kk + t]);
            qf[ks][1] = f2tf32(scale * Qb[(size_t)(g + 8) * DIMC + kk + t]);
            qf[ks][2] = f2tf32(scale * Qb[(size_t)g * DIMC + kk + t + 4]);
            qf[ks][3] = f2tf32(scale * Qb[(size_t)(g + 8) * DIMC + kk + t + 4]);
        }
    }

    float oacc[16][4];
    #pragma unroll
    for (int i = 0; i < 16; i++)
        #pragma unroll
        for (int j = 0; j < 4; j++) oacc[i][j] = 0.f;
    float m0 = -INFINITY, m1 = -INFINITY, l0 = 0.f, l1 = 0.f;

    for (int s0 = 0; s0 < SEQ; s0 += FBC) {
        __syncthreads();   // previous tile's Ks/Vs reads done
        // load K,V tiles (tf32-rounded). 64x128 each: 8 float4 per thread per tensor.
        #pragma unroll
        for (int i = 0; i < 8; i++) {
            int f = tid + i * 256;
            int r = f >> 5, c = (f & 31) * 4;
            float4 kv = *reinterpret_cast<const float4*>(
                &Kg[(size_t)(kbase + s0 + r) * KVDIM + kh * HD + c]);
            *reinterpret_cast<float4*>(&Ks[r][c]) =
                make_float4(f2tf32f(kv.x), f2tf32f(kv.y), f2tf32f(kv.z), f2tf32f(kv.w));
            float4 vv = *reinterpret_cast<const float4*>(
                &Vg[(size_t)(kbase + s0 + r) * KVDIM + kh * HD + c]);
            *reinterpret_cast<float4*>(&Vs[r][c]) =
                make_float4(f2tf32f(vv.x), f2tf32f(vv.y), f2tf32f(vv.z), f2tf32f(vv.w));
        }
        __syncthreads();

        // ---- S = Qw(16x128) @ K^T(128x64) ----
        float sacc[8][4];
        #pragma unroll
        for (int nt = 0; nt < 8; nt++)
            #pragma unroll
            for (int j = 0; j < 4; j++) sacc[nt][j] = 0.f;

        #pragma unroll
        for (int ks = 0; ks < 16; ks++) {
            const int kk = ks * 8;
            #pragma unroll
            for (int nt = 0; nt < 8; nt++) {
                uint32_t b0 = __float_as_uint(Ks[nt * 8 + g][kk + t]);
                uint32_t b1 = __float_as_uint(Ks[nt * 8 + g][kk + t + 4]);
                mma_tf32(sacc[nt], qf[ks][0], qf[ks][1], qf[ks][2], qf[ks][3], b0, b1);
            }
        }

        // ---- online softmax (warp-private rows g and g+8) ----
        float mx0 = -INFINITY, mx1 = -INFINITY;
        #pragma unroll
        for (int nt = 0; nt < 8; nt++) {
            mx0 = fmaxf(mx0, fmaxf(sacc[nt][0], sacc[nt][1]));
            mx1 = fmaxf(mx1, fmaxf(sacc[nt][2], sacc[nt][3]));
        }
        #pragma unroll
        for (int o = 1; o < 4; o <<= 1) {
            mx0 = fmaxf(mx0, __shfl_xor_sync(0xffffffffu, mx0, o));
            mx1 = fmaxf(mx1, __shfl_xor_sync(0xffffffffu, mx1, o));
        }
        const float nm0 = fmaxf(m0, mx0);
        const float nm1 = fmaxf(m1, mx1);

        float rs0 = 0.f, rs1 = 0.f;
        const int prow = warp * 16 + g;
        #pragma unroll
        for (int nt = 0; nt < 8; nt++) {
            float p00 = f2tf32f(__expf(sacc[nt][0] - nm0));
            float p01 = f2tf32f(__expf(sacc[nt][1] - nm0));
            float p10 = f2tf32f(__expf(sacc[nt][2] - nm1));
            float p11 = f2tf32f(__expf(sacc[nt][3] - nm1));
            rs0 += p00 + p01;
            rs1 += p10 + p11;
            int pc = nt * 8 + 2 * t;
            *reinterpret_cast<float2*>(&Ps[prow][pc])     = make_float2(p00, p01);
            *reinterpret_cast<float2*>(&Ps[prow + 8][pc]) = make_float2(p10, p11);
        }
        #pragma unroll
        for (int o = 1; o < 4; o <<= 1) {
            rs0 += __shfl_xor_sync(0xffffffffu, rs0, o);
            rs1 += __shfl_xor_sync(0xffffffffu, rs1, o);
        }
        const float a0 = __expf(m0 - nm0);
        const float a1 = __expf(m1 - nm1);
        l0 = l0 * a0 + rs0;
        l1 = l1 * a1 + rs1;
        m0 = nm0; m1 = nm1;
        #pragma unroll
        for (int nt = 0; nt < 16; nt++) {
            oacc[nt][0] *= a0; oacc[nt][1] *= a0;
            oacc[nt][2] *= a1; oacc[nt][3] *= a1;
        }
        __syncwarp();   // Ps rows are warp-private: warp-level visibility suffices

        // ---- O += P(16x64) @ V(64x128) ----
        #pragma unroll
        for (int ks = 0; ks < 8; ks++) {
            const int kk = ks * 8;
            uint32_t af0 = __float_as_uint(Ps[warp * 16 + g][kk + t]);
            uint32_t af1 = __float_as_uint(Ps[warp * 16 + g + 8][kk + t]);
            uint32_t af2 = __float_as_uint(Ps[warp * 16 + g][kk + t + 4]);
            uint32_t af3 = __float_as_uint(Ps[warp * 16 + g + 8][kk + t + 4]);
            #pragma unroll
            for (int nt = 0; nt < 16; nt++) {
                uint32_t b0 = __float_as_uint(Vs[kk + t][nt * 8 + g]);
                uint32_t b1 = __float_as_uint(Vs[kk + t + 4][nt * 8 + g]);
                mma_tf32(oacc[nt], af0, af1, af2, af3, b0, b1);
            }
        }
        __syncwarp();
    }

    // epilogue
    const float inv0 = 1.f / l0;
    const float inv1 = 1.f / l1;
    const int orow = q0 + warp * 16 + g;
    #pragma unroll
    for (int nt = 0; nt < 16; nt++) {
        int col = h * HD + nt * 8 + 2 * t;
        *reinterpret_cast<float2*>(&Og[(size_t)orow * DIMC + col]) =
            make_float2(oacc[nt][0] * inv0, oacc[nt][1] * inv0);
        *reinterpret_cast<float2*>(&Og[(size_t)(orow + 8) * DIMC + col]) =
            make_float2(oacc[nt][2] * inv1, oacc[nt][3] * inv1);
    }
}

// ---------------------------------------------------------------------------
extern "C" void kernel_launch(void* const* d_in, const int* in_sizes, int n_in,
                              void* d_out, int out_size)
{
    const float* x  = (const float*)d_in[0];
    const float* Wq = (const float*)d_in[1];
    const float* Wk = (const float*)d_in[2];
    const float* Wv = (const float*)d_in[3];
    const float* Wo = (const float*)d_in[4];
    float* out = (float*)d_out;

    float *q, *k, *v, *att;
    cudaGetSymbolAddress((void**)&q,   g_q);
    cudaGetSymbolAddress((void**)&k,   g_k);
    cudaGetSymbolAddress((void**)&v,   g_v);
    cudaGetSymbolAddress((void**)&att, g_att);

    cudaFuncSetAttribute(flash_tf32, cudaFuncAttributeMaxDynamicSharedMemorySize,
                         FLASH_SMEM_BYTES);

    dim3 blk(256);
    gemm_tf32<<<dim3(DIMC / 128,  MROWS / 128), blk>>>(x,   Wq, q,   MROWS, DIMC,  DIMC);
    gemm_tf32<<<dim3(KVDIM / 128, MROWS / 128), blk>>>(x,   Wk, k,   MROWS, KVDIM, DIMC);
    gemm_tf32<<<dim3(KVDIM / 128, MROWS / 128), blk>>>(x,   Wv, v,   MROWS, KVDIM, DIMC);
    flash_tf32<<<dim3(SEQ / FBR, NH, BATCH), blk, FLASH_SMEM_BYTES>>>(q, k, v, att);
    gemm_tf32<<<dim3(DIMC / 128,  MROWS / 128), blk>>>(att, Wo, out, MROWS, DIMC,  DIMC);
}

// round 3
// speedup vs baseline: 7.9822x; 2.5057x over previous
#include <cuda_runtime.h>
#include <cuda_fp16.h>
#include <math.h>
#include <stdint.h>

#define DIMC   2048
#define NH     16
#define NKV    4
#define HD     128
#define BATCH  2
#define SEQ    2048
#define MROWS  4096
#define KVDIM  512

// fp16 scratch (device globals; no cudaMalloc allowed)
__device__ __half g_xh [MROWS * DIMC];
__device__ __half g_Wqh[DIMC * DIMC];
__device__ __half g_Wkh[DIMC * KVDIM];
__device__ __half g_Wvh[DIMC * KVDIM];
__device__ __half g_Woh[DIMC * DIMC];
__device__ __half g_qh [MROWS * DIMC];
__device__ __half g_kh [MROWS * KVDIM];
__device__ __half g_vh [MROWS * KVDIM];
__device__ __half g_ah [MROWS * DIMC];

// ---------------------------------------------------------------------------
// helpers
// ---------------------------------------------------------------------------
__device__ __forceinline__ uint32_t smem_u32(const void* p) {
    return (uint32_t)__cvta_generic_to_shared(p);
}
__device__ __forceinline__ void cp16(uint32_t s, const void* g) {
    asm volatile("cp.async.cg.shared.global [%0], [%1], 16;" :: "r"(s), "l"(g));
}
__device__ __forceinline__ void cp_commit() {
    asm volatile("cp.async.commit_group;");
}
template<int N> __device__ __forceinline__ void cp_wait() {
    asm volatile("cp.async.wait_group %0;" :: "n"(N));
}
__device__ __forceinline__ void ldsm_x4(uint32_t& r0, uint32_t& r1, uint32_t& r2, uint32_t& r3, uint32_t a) {
    asm volatile("ldmatrix.sync.aligned.m8n8.x4.shared.b16 {%0,%1,%2,%3}, [%4];"
        : "=r"(r0), "=r"(r1), "=r"(r2), "=r"(r3) : "r"(a));
}
__device__ __forceinline__ void ldsm_x4t(uint32_t& r0, uint32_t& r1, uint32_t& r2, uint32_t& r3, uint32_t a) {
    asm volatile("ldmatrix.sync.aligned.m8n8.x4.trans.shared.b16 {%0,%1,%2,%3}, [%4];"
        : "=r"(r0), "=r"(r1), "=r"(r2), "=r"(r3) : "r"(a));
}
__device__ __forceinline__ void mma16816(float* c,
    uint32_t a0, uint32_t a1, uint32_t a2, uint32_t a3, uint32_t b0, uint32_t b1)
{
    asm volatile(
        "mma.sync.aligned.m16n8k16.row.col.f32.f16.f16.f32 "
        "{%0,%1,%2,%3}, {%4,%5,%6,%7}, {%8,%9}, {%0,%1,%2,%3};"
        : "+f"(c[0]), "+f"(c[1]), "+f"(c[2]), "+f"(c[3])
        : "r"(a0), "r"(a1), "r"(a2), "r"(a3), "r"(b0), "r"(b1));
}
__device__ __forceinline__ float ex2f(float x) {
    float y; asm("ex2.approx.ftz.f32 %0, %1;" : "=f"(y) : "f"(x)); return y;
}
__device__ __forceinline__ uint32_t h2u(__half2 h) { return *reinterpret_cast<uint32_t*>(&h); }

// ---------------------------------------------------------------------------
// fp32 -> fp16 conversion (n % 2048 == 0 for all our arrays)
// ---------------------------------------------------------------------------
__global__ __launch_bounds__(256) void f2h_kernel(
    const float* __restrict__ src, __half* __restrict__ dst, int n)
{
    int i = (blockIdx.x * 256 + threadIdx.x) * 8;
    if (i >= n) return;
    float4 a = *reinterpret_cast<const float4*>(src + i);
    float4 b = *reinterpret_cast<const float4*>(src + i + 4);
    __half2 h0 = __floats2half2_rn(a.x, a.y);
    __half2 h1 = __floats2half2_rn(a.z, a.w);
    __half2 h2 = __floats2half2_rn(b.x, b.y);
    __half2 h3 = __floats2half2_rn(b.z, b.w);
    uint4 o = make_uint4(h2u(h0), h2u(h1), h2u(h2), h2u(h3));
    *reinterpret_cast<uint4*>(dst + i) = o;
}

// ---------------------------------------------------------------------------
// fp16 GEMM: C = A(MxK) @ B(KxN), row-major, fp32 accumulate.
// 128x128 block tile, BK=32, 2-stage cp.async, 256 threads (8 warps 2x4).
// Warp tile 64x32; fragments via ldmatrix. F16OUT: store half2, else float2.
// ---------------------------------------------------------------------------
#define ASTR 40     // 32 + 8 halves pad
#define BSTR 136    // 128 + 8 halves pad

template<bool F16OUT>
__global__ __launch_bounds__(256, 2) void hgemm(
    const __half* __restrict__ A, const __half* __restrict__ B,
    void* __restrict__ Cv, int M, int N, int K)
{
    __shared__ __half As[2][128][ASTR];
    __shared__ __half Bs[2][32][BSTR];

    const int tid  = threadIdx.x;
    const int warp = tid >> 5;
    const int lane = tid & 31;
    const int g = lane >> 2, t = lane & 3;
    const int wm = warp & 1, wn = warp >> 1;
    const int bm = blockIdx.y * 128, bn = blockIdx.x * 128;

    float acc[4][4][4];
    #pragma unroll
    for (int i = 0; i < 4; i++)
        #pragma unroll
        for (int j = 0; j < 4; j++)
            #pragma unroll
            for (int r = 0; r < 4; r++) acc[i][j][r] = 0.f;

    auto load_tile = [&](int kt, int s) {
        const int k0 = kt * 32;
        #pragma unroll
        for (int i = 0; i < 2; i++) {           // A: 128x32 halves = 512 chunks
            int f = tid + i * 256;
            int r = f >> 2, c = (f & 3) * 8;
            cp16(smem_u32(&As[s][r][c]), A + (size_t)(bm + r) * K + k0 + c);
        }
        #pragma unroll
        for (int i = 0; i < 2; i++) {           // B: 32x128 halves = 512 chunks
            int f = tid + i * 256;
            int r = f >> 4, c = (f & 15) * 8;
            cp16(smem_u32(&Bs[s][r][c]), B + (size_t)(k0 + r) * N + bn + c);
        }
        cp_commit();
    };

    const int KT = K / 32;
    load_tile(0, 0);
    for (int kt = 0; kt < KT; kt++) {
        const int s = kt & 1;
        if (kt + 1 < KT) { load_tile(kt + 1, s ^ 1); cp_wait<1>(); }
        else             { cp_wait<0>(); }
        __syncthreads();

        #pragma unroll
        for (int ks = 0; ks < 2; ks++) {
            const int kk = ks * 16;
            uint32_t af[4][4];
            #pragma unroll
            for (int mt = 0; mt < 4; mt++) {
                int r0 = wm * 64 + mt * 16;
                uint32_t a = smem_u32(&As[s][r0 + (lane & 15)][kk + ((lane >> 4) << 3)]);
                ldsm_x4(af[mt][0], af[mt][1], af[mt][2], af[mt][3], a);
            }
            uint32_t bf[4][2];
            #pragma unroll
            for (int np = 0; np < 2; np++) {
                int c0 = wn * 32 + np * 16;
                uint32_t a = smem_u32(&Bs[s][kk + (lane & 7) + ((lane >> 3) & 1) * 8]
                                           [c0 + ((lane >> 4) << 3)]);
                ldsm_x4t(bf[2*np][0], bf[2*np][1], bf[2*np+1][0], bf[2*np+1][1], a);
            }
            #pragma unroll
            for (int mt = 0; mt < 4; mt++)
                #pragma unroll
                for (int nt = 0; nt < 4; nt++)
                    mma16816(acc[mt][nt], af[mt][0], af[mt][1], af[mt][2], af[mt][3],
                             bf[nt][0], bf[nt][1]);
        }
        __syncthreads();
    }

    #pragma unroll
    for (int mt = 0; mt < 4; mt++) {
        #pragma unroll
        for (int nt = 0; nt < 4; nt++) {
            int r0 = bm + wm * 64 + mt * 16 + g;
            int c0 = bn + wn * 32 + nt * 8 + 2 * t;
            if (F16OUT) {
                __half* C = (__half*)Cv;
                *reinterpret_cast<__half2*>(&C[(size_t)r0 * N + c0]) =
                    __floats2half2_rn(acc[mt][nt][0], acc[mt][nt][1]);
                *reinterpret_cast<__half2*>(&C[(size_t)(r0 + 8) * N + c0]) =
                    __floats2half2_rn(acc[mt][nt][2], acc[mt][nt][3]);
            } else {
                float* C = (float*)Cv;
                *reinterpret_cast<float2*>(&C[(size_t)r0 * N + c0]) =
                    make_float2(acc[mt][nt][0], acc[mt][nt][1]);
                *reinterpret_cast<float2*>(&C[(size_t)(r0 + 8) * N + c0]) =
                    make_float2(acc[mt][nt][2], acc[mt][nt][3]);
            }
        }
    }
}

// ---------------------------------------------------------------------------
// fp16 flash attention. Br=128, Bc=64, d=128. 8 warps, warp owns 16 q rows.
// Q fragments register-resident; P register-resident (S C-layout == PV A-layout);
// K/V tiles double-buffered via cp.async. Softmax in base-2 with the 1/sqrt(d)
// scale folded into the log2e constant.
// ---------------------------------------------------------------------------
#define FBC 64
#define KSTR 136
#define FLASH_SMEM (4 * FBC * KSTR * (int)sizeof(__half))   // 69632 B

__global__ __launch_bounds__(256, 1) void flash_h(
    const __half* __restrict__ Qh, const __half* __restrict__ Kh,
    const __half* __restrict__ Vh, __half* __restrict__ Oh)
{
    extern __shared__ __half fsm[];
    __half (*Ks)[FBC][KSTR] = reinterpret_cast<__half(*)[FBC][KSTR]>(fsm);
    __half (*Vs)[FBC][KSTR] = reinterpret_cast<__half(*)[FBC][KSTR]>(fsm + 2 * FBC * KSTR);
    __half (*Qst)[KSTR]     = reinterpret_cast<__half(*)[KSTR]>(fsm);   // 128x136, reuses Ks

    const int tid  = threadIdx.x;
    const int warp = tid >> 5;
    const int lane = tid & 31;
    const int g = lane >> 2, t = lane & 3;

    const int qb = blockIdx.x, h = blockIdx.y, b = blockIdx.z;
    const int khd = h >> 2;
    const int q0 = b * SEQ + qb * 128;
    const __half* Qb = Qh + (size_t)q0 * DIMC + h * HD;
    const __half* Kb = Kh + (size_t)b * SEQ * KVDIM + khd * HD;
    const __half* Vb = Vh + (size_t)b * SEQ * KVDIM + khd * HD;
    const float CC = 0.12751744154070513f;   // (1/sqrt(128)) * log2(e)

    // ---- stage Q, load register fragments ----
    #pragma unroll
    for (int i = 0; i < 8; i++) {
        int f = tid + i * 256;
        int r = f >> 4, c = (f & 15) * 8;
        cp16(smem_u32(&Qst[r][c]), Qb + (size_t)r * DIMC + c);
    }
    cp_commit(); cp_wait<0>();
    __syncthreads();
    uint32_t qf[8][4];
    #pragma unroll
    for (int ks = 0; ks < 8; ks++) {
        uint32_t a = smem_u32(&Qst[warp * 16 + (lane & 15)][ks * 16 + ((lane >> 4) << 3)]);
        ldsm_x4(qf[ks][0], qf[ks][1], qf[ks][2], qf[ks][3], a);
    }
    __syncthreads();   // Q reads done before K/V cp.async overwrites

    float oacc[16][4];
    #pragma unroll
    for (int i = 0; i < 16; i++)
        #pragma unroll
        for (int j = 0; j < 4; j++) oacc[i][j] = 0.f;
    float m0 = -INFINITY, m1 = -INFINITY, l0 = 0.f, l1 = 0.f;

    auto load_kv = [&](int it, int s) {
        const int s0 = it * FBC;
        #pragma unroll
        for (int i = 0; i < 4; i++) {
            int f = tid + i * 256;
            int r = f >> 4, c = (f & 15) * 8;
            cp16(smem_u32(&Ks[s][r][c]), Kb + (size_t)(s0 + r) * KVDIM + c);
            cp16(smem_u32(&Vs[s][r][c]), Vb + (size_t)(s0 + r) * KVDIM + c);
        }
        cp_commit();
    };

    const int NT = SEQ / FBC;   // 32
    load_kv(0, 0);
    for (int it = 0; it < NT; it++) {
        const int s = it & 1;
        if (it + 1 < NT) { load_kv(it + 1, s ^ 1); cp_wait<1>(); }
        else             { cp_wait<0>(); }
        __syncthreads();

        // ---- S = Q @ K^T  (16x64 per warp) ----
        float sacc[8][4];
        #pragma unroll
        for (int nt = 0; nt < 8; nt++)
            #pragma unroll
            for (int j = 0; j < 4; j++) sacc[nt][j] = 0.f;

        #pragma unroll
        for (int ks = 0; ks < 8; ks++) {
            const int kk = ks * 16;
            uint32_t bf[8][2];
            #pragma unroll
            for (int np = 0; np < 4; np++) {
                uint32_t a = smem_u32(&Ks[s][np * 16 + (lane & 7) + ((lane >> 4) << 3)]
                                           [kk + ((lane >> 3) & 1) * 8]);
                ldsm_x4(bf[2*np][0], bf[2*np][1], bf[2*np+1][0], bf[2*np+1][1], a);
            }
            #pragma unroll
            for (int nt = 0; nt < 8; nt++)
                mma16816(sacc[nt], qf[ks][0], qf[ks][1], qf[ks][2], qf[ks][3],
                         bf[nt][0], bf[nt][1]);
        }

        // ---- online softmax (rows g and g+8 of this warp) ----
        float mx0 = -INFINITY, mx1 = -INFINITY;
        #pragma unroll
        for (int nt = 0; nt < 8; nt++) {
            mx0 = fmaxf(mx0, fmaxf(sacc[nt][0], sacc[nt][1]));
            mx1 = fmaxf(mx1, fmaxf(sacc[nt][2], sacc[nt][3]));
        }
        #pragma unroll
        for (int o = 1; o < 4; o <<= 1) {
            mx0 = fmaxf(mx0, __shfl_xor_sync(0xffffffffu, mx0, o));
            mx1 = fmaxf(mx1, __shfl_xor_sync(0xffffffffu, mx1, o));
        }
        const float nm0 = fmaxf(m0, mx0 * CC);
        const float nm1 = fmaxf(m1, mx1 * CC);

        float rs0 = 0.f, rs1 = 0.f;
        uint32_t pa[4][4];     // PV A-fragments, straight from S accumulators
        #pragma unroll
        for (int nt = 0; nt < 8; nt++) {
            float p0 = ex2f(fmaf(sacc[nt][0], CC, -nm0));
            float p1 = ex2f(fmaf(sacc[nt][1], CC, -nm0));
            float p2 = ex2f(fmaf(sacc[nt][2], CC, -nm1));
            float p3 = ex2f(fmaf(sacc[nt][3], CC, -nm1));
            __half2 h01 = __floats2half2_rn(p0, p1);
            __half2 h23 = __floats2half2_rn(p2, p3);
            float2 q01 = __half22float2(h01);
            float2 q23 = __half22float2(h23);
            rs0 += q01.x + q01.y;
            rs1 += q23.x + q23.y;
            const int j = nt >> 1;
            if ((nt & 1) == 0) { pa[j][0] = h2u(h01); pa[j][1] = h2u(h23); }
            else               { pa[j][2] = h2u(h01); pa[j][3] = h2u(h23); }
        }
        #pragma unroll
        for (int o = 1; o < 4; o <<= 1) {
            rs0 += __shfl_xor_sync(0xffffffffu, rs0, o);
            rs1 += __shfl_xor_sync(0xffffffffu, rs1, o);
        }
        const float a0 = ex2f(m0 - nm0);
        const float a1 = ex2f(m1 - nm1);
        l0 = l0 * a0 + rs0;
        l1 = l1 * a1 + rs1;
        m0 = nm0; m1 = nm1;
        #pragma unroll
        for (int nt = 0; nt < 16; nt++) {
            oacc[nt][0] *= a0; oacc[nt][1] *= a0;
            oacc[nt][2] *= a1; oacc[nt][3] *= a1;
        }

        // ---- O += P @ V  (16x128 per warp) ----
        #pragma unroll
        for (int j = 0; j < 4; j++) {
            const int kk = j * 16;
            uint32_t vb[16][2];
            #pragma unroll
            for (int np = 0; np < 8; np++) {
                uint32_t a = smem_u32(&Vs[s][kk + (lane & 7) + ((lane >> 3) & 1) * 8]
                                           [np * 16 + ((lane >> 4) << 3)]);
                ldsm_x4t(vb[2*np][0], vb[2*np][1], vb[2*np+1][0], vb[2*np+1][1], a);
            }
            #pragma unroll
            for (int nt = 0; nt < 16; nt++)
                mma16816(oacc[nt], pa[j][0], pa[j][1], pa[j][2], pa[j][3],
                         vb[nt][0], vb[nt][1]);
        }
        __syncthreads();   // tile fully consumed before its buffer is refilled
    }

    // ---- epilogue: normalize, store fp16 ----
    const float inv0 = 1.f / l0;
    const float inv1 = 1.f / l1;
    const int orow = q0 + warp * 16 + g;
    #pragma unroll
    for (int nt = 0; nt < 16; nt++) {
        int col = h * HD + nt * 8 + 2 * t;
        *reinterpret_cast<__half2*>(&Oh[(size_t)orow * DIMC + col]) =
            __floats2half2_rn(oacc[nt][0] * inv0, oacc[nt][1] * inv0);
        *reinterpret_cast<__half2*>(&Oh[(size_t)(orow + 8) * DIMC + col]) =
            __floats2half2_rn(oacc[nt][2] * inv1, oacc[nt][3] * inv1);
    }
}

// ---------------------------------------------------------------------------
extern "C" void kernel_launch(void* const* d_in, const int* in_sizes, int n_in,
                              void* d_out, int out_size)
{
    const float* x  = (const float*)d_in[0];
    const float* Wq = (const float*)d_in[1];
    const float* Wk = (const float*)d_in[2];
    const float* Wv = (const float*)d_in[3];
    const float* Wo = (const float*)d_in[4];
    float* out = (float*)d_out;

    __half *xh, *Wqh, *Wkh, *Wvh, *Woh, *qh, *kh, *vh, *ah;
    cudaGetSymbolAddress((void**)&xh,  g_xh);
    cudaGetSymbolAddress((void**)&Wqh, g_Wqh);
    cudaGetSymbolAddress((void**)&Wkh, g_Wkh);
    cudaGetSymbolAddress((void**)&Wvh, g_Wvh);
    cudaGetSymbolAddress((void**)&Woh, g_Woh);
    cudaGetSymbolAddress((void**)&qh,  g_qh);
    cudaGetSymbolAddress((void**)&kh,  g_kh);
    cudaGetSymbolAddress((void**)&vh,  g_vh);
    cudaGetSymbolAddress((void**)&ah,  g_ah);

    cudaFuncSetAttribute(flash_h, cudaFuncAttributeMaxDynamicSharedMemorySize, FLASH_SMEM);

    // fp32 -> fp16 conversions
    auto cvt = [&](const float* s, __half* d, int n) {
        f2h_kernel<<<n / 8 / 256, 256>>>(s, d, n);
    };
    cvt(x,  xh,  MROWS * DIMC);
    cvt(Wq, Wqh, DIMC * DIMC);
    cvt(Wk, Wkh, DIMC * KVDIM);
    cvt(Wv, Wvh, DIMC * KVDIM);
    cvt(Wo, Woh, DIMC * DIMC);

    dim3 blk(256);
    hgemm<true><<<dim3(DIMC / 128,  MROWS / 128), blk>>>(xh, Wqh, qh, MROWS, DIMC,  DIMC);
    hgemm<true><<<dim3(KVDIM / 128, MROWS / 128), blk>>>(xh, Wkh, kh, MROWS, KVDIM, DIMC);
    hgemm<true><<<dim3(KVDIM / 128, MROWS / 128), blk>>>(xh, Wvh, vh, MROWS, KVDIM, DIMC);

    flash_h<<<dim3(SEQ / 128, NH, BATCH), blk, FLASH_SMEM>>>(qh, kh, vh, ah);

    hgemm<false><<<dim3(DIMC / 128, MROWS / 128), blk>>>(ah, Woh, out, MROWS, DIMC, DIMC);
}